// round 2
// baseline (speedup 1.0000x reference)
#include <cuda_runtime.h>
#include <cuda_bf16.h>
#include <cstdint>

// Problem constants (LengthRegulator_42691974922415):
//   pred_duration:           [B=32, L=512] int32, values in [0, 8)
//   phoneme_hidden_sequence: [B=32, L=512, D=384] float32
//   output:                  [B=32, T=L*7=3584, D=384] float32
static constexpr int B  = 32;
static constexpr int L  = 512;
static constexpr int D  = 384;
static constexpr int T  = 3584;       // L * (DUR_MAX-1)
static constexpr int D4 = D / 4;      // 96 float4 per row

// Scratch: frame -> source hidden-row id (b*L + l), or -1 for zero frames.
// 32*3584 ints = 458 KB static device memory (no runtime allocation).
__device__ int g_frame_idx[B * T];

// ---------------------------------------------------------------------------
// Kernel 1: per-batch duration scan + frame-index scatter.
// One block per batch, 512 threads (one per phoneme).
// ---------------------------------------------------------------------------
__global__ void __launch_bounds__(L) build_index_kernel(const int* __restrict__ dur)
{
    const int b   = blockIdx.x;
    const int tid = threadIdx.x;           // phoneme index l
    const int lane = tid & 31;
    const int w    = tid >> 5;             // warp id, 0..15

    int d = dur[b * L + tid];

    // Warp-level inclusive scan.
    int x = d;
    #pragma unroll
    for (int o = 1; o < 32; o <<= 1) {
        int y = __shfl_up_sync(0xffffffffu, x, o);
        if (lane >= o) x += y;
    }

    __shared__ int wsum[16];
    if (lane == 31) wsum[w] = x;
    __syncthreads();

    // Scan the 16 warp totals (warp 0, full-mask shuffles).
    if (w == 0) {
        int s = (lane < 16) ? wsum[lane] : 0;
        #pragma unroll
        for (int o = 1; o < 16; o <<= 1) {
            int y = __shfl_up_sync(0xffffffffu, s, o);
            if (lane >= o) s += y;
        }
        if (lane < 16) wsum[lane] = s;
    }
    __syncthreads();

    const int incl  = x + (w > 0 ? wsum[w - 1] : 0);  // inclusive cumsum
    const int start = incl - d;                       // exclusive start frame

    // Fill this batch's frame map with -1 (zero frames), then scatter.
    int* fi = g_frame_idx + b * T;
    #pragma unroll
    for (int t = tid; t < T; t += L) fi[t] = -1;
    __syncthreads();

    const int src = b * L + tid;
    for (int k = 0; k < d; ++k)           // d <= 7
        fi[start + k] = src;
}

// ---------------------------------------------------------------------------
// Kernel 2: streaming expand. One float4 per thread, exact-cover grid.
//   total float4 = B*T*D4 = 11,010,048 = 43008 blocks * 256 threads
// Stores use .cs (evict-first) so the 176 MB output stream does not evict
// the 25 MB L2-resident hidden tensor.
// ---------------------------------------------------------------------------
__global__ void __launch_bounds__(256) expand_kernel(const float4* __restrict__ hid,
                                                     float4* __restrict__ out)
{
    const int i   = blockIdx.x * 256 + threadIdx.x;
    const int row = i / D4;                // frame row (b*T + t)
    const int c   = i - row * D4;          // float4 column within row

    const int src = __ldg(&g_frame_idx[row]);

    float4 v = make_float4(0.f, 0.f, 0.f, 0.f);
    if (src >= 0)
        v = __ldg(&hid[src * D4 + c]);

    __stcs(&out[i], v);
}

// ---------------------------------------------------------------------------
extern "C" void kernel_launch(void* const* d_in, const int* in_sizes, int n_in,
                              void* d_out, int out_size)
{
    const int*    dur = (const int*)d_in[0];            // [B, L] int32
    const float4* hid = (const float4*)d_in[1];         // [B, L, D] f32 as float4
    float4*       out = (float4*)d_out;                 // [B, T, D] f32 as float4

    build_index_kernel<<<B, L>>>(dur);

    const int n4 = B * T * D4;            // 11,010,048
    expand_kernel<<<n4 / 256, 256>>>(hid, out);
}

// round 4
// speedup vs baseline: 1.1092x; 1.1092x over previous
#include <cuda_runtime.h>
#include <cuda_bf16.h>
#include <cstdint>

// Problem constants (LengthRegulator_42691974922415):
//   pred_duration:           [B=32, L=512] int32, values in [0, 8)
//   phoneme_hidden_sequence: [B=32, L=512, D=384] float32
//   output:                  [B=32, T=L*7=3584, D=384] float32
static constexpr int B  = 32;
static constexpr int L  = 512;
static constexpr int D  = 384;
static constexpr int T  = 3584;       // L * (DUR_MAX-1)
static constexpr int D4 = D / 4;      // 96 float4 per row

// Scratch: frame -> source hidden-row id (b*L + l), or -1 for zero frames.
// 32*3584 ints = 458 KB static device memory (no runtime allocation).
__device__ int g_frame_idx[B * T];

// ---------------------------------------------------------------------------
// Kernel 1: per-batch duration scan + frame-index scatter.
// One block per batch, 512 threads (one per phoneme).
// ---------------------------------------------------------------------------
__global__ void __launch_bounds__(L) build_index_kernel(const int* __restrict__ dur)
{
    const int b   = blockIdx.x;
    const int tid = threadIdx.x;           // phoneme index l
    const int lane = tid & 31;
    const int w    = tid >> 5;             // warp id, 0..15

    int d = dur[b * L + tid];

    // Warp-level inclusive scan.
    int x = d;
    #pragma unroll
    for (int o = 1; o < 32; o <<= 1) {
        int y = __shfl_up_sync(0xffffffffu, x, o);
        if (lane >= o) x += y;
    }

    __shared__ int wsum[16];
    if (lane == 31) wsum[w] = x;
    __syncthreads();

    // Scan the 16 warp totals (warp 0, full-mask shuffles).
    if (w == 0) {
        int s = (lane < 16) ? wsum[lane] : 0;
        #pragma unroll
        for (int o = 1; o < 16; o <<= 1) {
            int y = __shfl_up_sync(0xffffffffu, s, o);
            if (lane >= o) s += y;
        }
        if (lane < 16) wsum[lane] = s;
    }
    __syncthreads();

    const int incl  = x + (w > 0 ? wsum[w - 1] : 0);  // inclusive cumsum
    const int start = incl - d;                       // exclusive start frame

    // Fill this batch's frame map with -1 (zero frames), then scatter.
    int* fi = g_frame_idx + b * T;
    #pragma unroll
    for (int t = tid; t < T; t += L) fi[t] = -1;
    __syncthreads();

    const int src = b * L + tid;
    for (int k = 0; k < d; ++k)           // d <= 7
        fi[start + k] = src;
}

// ---------------------------------------------------------------------------
// Kernel 2: streaming expand with ILP=4.
//   total float4 = B*T*D4 = 11,010,048 = 10752 blocks * 256 threads * 4
// Each thread handles 4 float4s at (base + tid + k*256): every store slice is
// a fully-coalesced 256-thread span; 4 independent idx-loads / hid-loads /
// stores per thread give MLP>=4 to hide DRAM latency.
// Stores use .cs (evict-first) so the 176 MB output stream does not evict
// the 25 MB L2-resident hidden tensor.
// ---------------------------------------------------------------------------
static constexpr int ILP = 4;

__global__ void __launch_bounds__(256) expand_kernel(const float4* __restrict__ hid,
                                                     float4* __restrict__ out)
{
    const int base = blockIdx.x * (256 * ILP) + threadIdx.x;

    int   idx[ILP];
    int   col[ILP];

    #pragma unroll
    for (int k = 0; k < ILP; ++k) {
        const int i   = base + k * 256;
        const int row = i / D4;            // frame row (b*T + t)
        col[k]        = i - row * D4;      // float4 column within row
        idx[k]        = __ldg(&g_frame_idx[row]);   // 4 independent loads
    }

    float4 v[ILP];
    #pragma unroll
    for (int k = 0; k < ILP; ++k) {
        v[k] = make_float4(0.f, 0.f, 0.f, 0.f);
        if (idx[k] >= 0)
            v[k] = __ldg(&hid[idx[k] * D4 + col[k]]);  // 4 independent gathers
    }

    #pragma unroll
    for (int k = 0; k < ILP; ++k)
        __stcs(&out[base + k * 256], v[k]);            // 4 independent streams
}

// ---------------------------------------------------------------------------
extern "C" void kernel_launch(void* const* d_in, const int* in_sizes, int n_in,
                              void* d_out, int out_size)
{
    const int*    dur = (const int*)d_in[0];            // [B, L] int32
    const float4* hid = (const float4*)d_in[1];         // [B, L, D] f32 as float4
    float4*       out = (float4*)d_out;                 // [B, T, D] f32 as float4

    build_index_kernel<<<B, L>>>(dur);

    const int n4 = B * T * D4;            // 11,010,048
    expand_kernel<<<n4 / (256 * ILP), 256>>>(hid, out);
}